// round 17
// baseline (speedup 1.0000x reference)
#include <cuda_runtime.h>

#define C_DIM 4096
#define N_F 8
#define NPAIR 36            // 8*9/2, i<=j
#define EPS_F 1e-8f
#define NTILE 32            // 4096 / 128
#define NROWB 512           // (u-tile, factor, v-half) rowsum blocks
#define NCROSSB (528 * 2)   // 1056: triangle tiles x 2 v-halves
#define NBLOCKS (NROWB + NCROSSB)   // 1568
#define NSTOT (2 * NPAIR + N_F)     // [0,36): rowdots  [36,72): cross  [72,80): fsum

typedef unsigned long long u64;

// Device globals (statics start zero; tickets/accumulators reset for graph replay).
__device__ float g_rowsum2[2][N_F * C_DIM];  // halved rowsums
__device__ float g_stot[NSTOT];
__device__ unsigned int g_tile_ctr[NTILE];
__device__ unsigned int g_ctr = 0;

// ---- packed f32x2 helpers (sm_103a) ----
__device__ __forceinline__ u64 pack2(float lo, float hi) {
    u64 r; asm("mov.b64 %0, {%1, %2};" : "=l"(r) : "f"(lo), "f"(hi)); return r;
}
__device__ __forceinline__ void unpack2(float& lo, float& hi, u64 v) {
    asm("mov.b64 {%0, %1}, %2;" : "=f"(lo), "=f"(hi) : "l"(v));
}
__device__ __forceinline__ u64 add2(u64 a, u64 b) {
    u64 d; asm("add.rn.f32x2 %0, %1, %2;" : "=l"(d) : "l"(a), "l"(b)); return d;
}
__device__ __forceinline__ u64 fma2(u64 a, u64 b, u64 c) {
    u64 d; asm("fma.rn.f32x2 %0, %1, %2, %3;" : "=l"(d) : "l"(a), "l"(b), "l"(c)); return d;
}
__device__ __forceinline__ u64 abs2(u64 a) {
    u64 d; asm("and.b64 %0, %1, 0x7FFFFFFF7FFFFFFF;" : "=l"(d) : "l"(a)); return d;
}

// Release ticket add (no L1-flushing fence) + winner-side acquire.
__device__ __forceinline__ unsigned atomic_add_release(unsigned* p, unsigned v) {
    unsigned old;
    asm volatile("atom.add.release.gpu.u32 %0, [%1], %2;"
                 : "=r"(old) : "l"(p), "r"(v) : "memory");
    return old;
}
__device__ __forceinline__ void fence_acquire_gpu() {
    asm volatile("fence.acq_rel.gpu;" ::: "memory");
}

__global__ __launch_bounds__(128, 5) void main_kernel(const float* __restrict__ x,
                                                      float* __restrict__ out) {
    __shared__ union {
        float row[4096];             // rowsum: negated v-half (2048 used), u64-readable
        struct {
            __align__(16) float2 v[32 * N_F];  // cross: negated packed v-pairs [vp][f]
            float red[4][NPAIR];               // per-warp pair partials
        } c;
        float tred[4][NPAIR + N_F];  // tile-reduce partials
        struct {
            float sdc[NPAIR];        // final math
            float sm[N_F];
        } e;
    } sh;
    __shared__ unsigned sh_rank;

    const int tid = threadIdx.x;
    const int bid = blockIdx.x;
    const int lane = tid & 31;
    const int warp = tid >> 5;

    if (bid < NROWB) {
        // ---------- rowsum path: half-row blocks, packed f32x2 ----------
        const int rb = bid;                 // [0, 512)
        const int ut = rb >> 4;             // u-tile 0..31
        const int f = (rb >> 1) & 7;        // factor
        const int half = rb & 1;            // v-half
        const float* xf = x + f * C_DIM;
        const int vb = half * 2048;

        for (int i = tid; i < 2048; i += 128) sh.row[i] = -xf[vb + i];

        const int u = ut * 128 + tid;
        const float xu = xf[u];
        const u64 xu2 = pack2(xu, xu);
        __syncthreads();

        u64 s0 = 0ull, s1 = 0ull, s2 = 0ull, s3 = 0ull;
        const ulonglong2* row2 = (const ulonglong2*)sh.row;
#pragma unroll 4
        for (int p = 0; p < 512; p += 2) {
            ulonglong2 qa = row2[p];
            ulonglong2 qb = row2[p + 1];
            s0 = add2(s0, abs2(add2(xu2, qa.x)));
            s1 = add2(s1, abs2(add2(xu2, qa.y)));
            s2 = add2(s2, abs2(add2(xu2, qb.x)));
            s3 = add2(s3, abs2(add2(xu2, qb.y)));
        }
        float a0, b0, a1, b1, a2v, b2v, a3, b3;
        unpack2(a0, b0, s0); unpack2(a1, b1, s1);
        unpack2(a2v, b2v, s2); unpack2(a3, b3, s3);
        __stcg(&g_rowsum2[half][f * C_DIM + u],
               ((a0 + b0) + (a1 + b1)) + ((a2v + b2v) + (a3 + b3)));

        // ---- per-u-tile ticket: 16th block reduces the rowdots ----
        if (tid == 0) sh_rank = atomic_add_release(&g_tile_ctr[ut], 1u);
        __syncthreads();
        if (sh_rank == 15u) {
            fence_acquire_gpu();
            float r[N_F];
#pragma unroll
            for (int ff = 0; ff < N_F; ff++)
                r[ff] = __ldcg(&g_rowsum2[0][ff * C_DIM + u])
                      + __ldcg(&g_rowsum2[1][ff * C_DIM + u]);

            __syncthreads();   // smem union handoff (row -> tred)
            int k = 0;
#pragma unroll
            for (int i = 0; i < N_F; i++) {
#pragma unroll
                for (int j = i; j < N_F; j++) {
                    float v = r[i] * r[j];
                    for (int o = 16; o; o >>= 1) v += __shfl_down_sync(0xffffffffu, v, o);
                    if (lane == 0) sh.tred[warp][k] = v;
                    k++;
                }
            }
#pragma unroll
            for (int ff = 0; ff < N_F; ff++) {
                float v = r[ff];
                for (int o = 16; o; o >>= 1) v += __shfl_down_sync(0xffffffffu, v, o);
                if (lane == 0) sh.tred[warp][NPAIR + ff] = v;
            }
            __syncthreads();
            if (tid < NPAIR + N_F) {
                float v = sh.tred[0][tid] + sh.tred[1][tid]
                        + sh.tred[2][tid] + sh.tred[3][tid];
                int dst = (tid < NPAIR) ? tid : (2 * NPAIR + (tid - NPAIR));
                atomicAdd(&g_stot[dst], v);
            }
            if (tid == 0) g_tile_ctr[ut] = 0;
        }
    } else {
        // ---------- cross path: packed f32x2, two passes of 18 pairs ----------
        const int ci = bid - NROWB;         // [0, 1056)
        const int tile = ci >> 1;
        const int vh = ci & 1;
        int rem = tile, ti = 0;
        while (rem >= NTILE - ti) { rem -= NTILE - ti; ti++; }
        const int tj = ti + rem;
        const int vb = tj * 128 + vh * 64;  // 64 v's = 32 packed pairs

        // Stage negated packed v-pairs: sh.c.v[vp*8 + f] = (-x[f][vb+2vp], -x[f][vb+2vp+1])
        for (int i = tid; i < 32 * N_F; i += 128) {
            int f = i >> 5, vp = i & 31;
            float2 p = *(const float2*)&x[f * C_DIM + vb + 2 * vp];
            sh.c.v[vp * N_F + f] = make_float2(-p.x, -p.y);
        }

        const int u = ti * 128 + tid;
        u64 xu2[N_F];
#pragma unroll
        for (int f = 0; f < N_F; f++) {
            float xv = x[f * C_DIM + u];
            xu2[f] = pack2(xv, xv);
        }
        __syncthreads();

        // Pass macro body: pairs [KLO, KHI), diffs for factors [FLO, 8).
        // Group 1: k 0..17  = (0,0..7),(1,1..7),(2,2),(2,3),(2,4)   -> FLO=0
        // Group 2: k 18..35 = (2,5),(2,6),(2,7),(3,3..7),...,(7,7)  -> FLO=2
#define CROSS_PASS(KLO, KHI, FLO)                                              \
        {                                                                      \
            u64 acc2[(KHI) - (KLO)];                                           \
            _Pragma("unroll")                                                  \
            for (int k = 0; k < (KHI) - (KLO); k++) acc2[k] = 0ull;            \
            _Pragma("unroll 1")                                                \
            for (int vp = 0; vp < 32; vp++) {                                  \
                const ulonglong2* vv = (const ulonglong2*)&sh.c.v[vp * N_F];   \
                u64 xv2[N_F];                                                  \
                _Pragma("unroll")                                              \
                for (int q = (FLO) / 2; q < 4; q++) {                          \
                    ulonglong2 t = vv[q];                                      \
                    xv2[2 * q] = t.x; xv2[2 * q + 1] = t.y;                    \
                }                                                              \
                u64 a2[N_F];                                                   \
                _Pragma("unroll")                                              \
                for (int f = (FLO); f < N_F; f++)                              \
                    a2[f] = abs2(add2(xu2[f], xv2[f]));                        \
                int k = 0;                                                     \
                _Pragma("unroll")                                              \
                for (int i = 0; i < N_F; i++) {                                \
                    _Pragma("unroll")                                          \
                    for (int j = i; j < N_F; j++) {                            \
                        if (k >= (KLO) && k < (KHI))                           \
                            acc2[k - (KLO)] = fma2(a2[i], a2[j], acc2[k - (KLO)]); \
                        k++;                                                   \
                    }                                                          \
                }                                                              \
            }                                                                  \
            _Pragma("unroll")                                                  \
            for (int k = 0; k < (KHI) - (KLO); k++) {                          \
                float lo, hi; unpack2(lo, hi, acc2[k]);                        \
                float v = lo + hi;                                             \
                for (int o = 16; o; o >>= 1) v += __shfl_down_sync(0xffffffffu, v, o); \
                if (lane == 0) sh.c.red[warp][(KLO) + k] = v;                  \
            }                                                                  \
        }

        CROSS_PASS(0, 18, 0)
        CROSS_PASS(18, 36, 2)
#undef CROSS_PASS

        // Diagonal tiles internally symmetric: weight 0.5 (self terms are 0).
        const float w = (ti == tj) ? 0.5f : 1.0f;
        __syncthreads();
        if (tid < NPAIR) {
            float v = (sh.c.red[0][tid] + sh.c.red[1][tid]
                     + sh.c.red[2][tid] + sh.c.red[3][tid]) * w;
            atomicAdd(&g_stot[NPAIR + tid], v);
        }
    }

    // ---------------- global ticket: last block does the 8x8 math ----------------
    if (tid == 0) sh_rank = atomic_add_release(&g_ctr, 1u);
    __syncthreads();
    if (sh_rank != NBLOCKS - 1) return;

    fence_acquire_gpu();

    const float fC = (float)C_DIM;
    const float invC2 = 1.0f / (fC * fC);

    __syncthreads();   // smem union handoff
    if (tid < N_F) sh.e.sm[tid] = __ldcg(&g_stot[2 * NPAIR + tid]) * invC2;
    __syncthreads();

    if (tid < NPAIR) {
        int kk = tid, i = 0;
        while (kk >= N_F - i) { kk -= N_F - i; i++; }
        int j = i + kk;
        // S = 2*cross_tri/C^2 - 2*rowdot/C^3 + m_i*m_j
        float s = 2.0f * __ldcg(&g_stot[NPAIR + tid]) * invC2
                - 2.0f * __ldcg(&g_stot[tid]) * invC2 / fC
                + sh.e.sm[i] * sh.e.sm[j];
        sh.e.sdc[tid] = sqrtf(fmaxf(s, 0.0f) + EPS_F);
    }
    __syncthreads();

    if (tid == 0) {
        float cor = 0.0f;
        for (int i = 0; i < N_F; i++) {
            int di = i * N_F - (i * (i - 1)) / 2;        // k(i,i)
            for (int j = i + 1; j < N_F; j++) {
                int dj = j * N_F - (j * (j - 1)) / 2;    // k(j,j)
                int kij = di + (j - i);                   // k(i,j)
                cor += sh.e.sdc[kij] / sqrtf(sh.e.sdc[di] * sh.e.sdc[dj] + EPS_F);
            }
        }
        out[0] = cor;
    }
    __syncthreads();

    // Reset accumulators/ticket for next graph replay (all reads done above).
    if (tid < NSTOT) g_stot[tid] = 0.0f;
    if (tid == 0) g_ctr = 0;
}

extern "C" void kernel_launch(void* const* d_in, const int* in_sizes, int n_in,
                              void* d_out, int out_size) {
    const float* x = (const float*)d_in[0];
    float* out = (float*)d_out;
    main_kernel<<<NBLOCKS, 128>>>(x, out);
}